// round 13
// baseline (speedup 1.0000x reference)
#include <cuda_runtime.h>
#include <cuda_fp16.h>
#include <cstdint>

#define BB 64
#define NN 512
#define DD 1024
#define ROWS (BB * NN)   // 32768

// ---------------------------------------------------------------------------
// Device scratch (no runtime allocation allowed)
// ---------------------------------------------------------------------------
__device__ __half g_Dh [(size_t)ROWS * DD];
__device__ __half g_Hh [(size_t)ROWS * DD];
__device__ __half g_DUh[(size_t)ROWS * DD];
__device__ __half g_Ut [(size_t)DD * DD];    // U^T (N-major rows, K contiguous)
__device__ float g_bx[ROWS];
__device__ float g_by[ROWS];
__device__ float g_Ucol[DD];                 // U[:,1024] packed, aligned
__device__ float g_Wdc[DD];                  // W[1025:2049] packed, aligned

// ---------------------------------------------------------------------------
// Helpers
// ---------------------------------------------------------------------------
__device__ __forceinline__ uint32_t smem_u32(const void* p) {
    uint32_t a;
    asm("{ .reg .u64 t; cvta.to.shared.u64 t, %1; cvt.u32.u64 %0, t; }" : "=r"(a) : "l"(p));
    return a;
}

__device__ __forceinline__ void cp_async16(uint32_t dst, const void* src) {
    asm volatile("cp.async.cg.shared.global [%0], [%1], 16;" :: "r"(dst), "l"(src));
}

#define CP_COMMIT() asm volatile("cp.async.commit_group;")

// Swizzled smem address: off = row*128 + col16*16, XOR bits[6:4] with row&7
__device__ __forceinline__ uint32_t sw_addr(uint32_t base, int row, int col16) {
    uint32_t off = (uint32_t)(row * 128 + col16 * 16);
    return base + (off ^ (((uint32_t)row & 7u) << 4));
}

#define LDSM4(r0, r1, r2, r3, addr) \
    asm volatile("ldmatrix.sync.aligned.m8n8.x4.shared.b16 {%0,%1,%2,%3}, [%4];" \
                 : "=r"(r0), "=r"(r1), "=r"(r2), "=r"(r3) : "r"(addr))

#define MMA16816(c, a0, a1, a2, a3, b0, b1) \
    asm volatile("mma.sync.aligned.m16n8k16.row.col.f32.f16.f16.f32 " \
                 "{%0,%1,%2,%3}, {%4,%5,%6,%7}, {%8,%9}, {%0,%1,%2,%3};" \
                 : "+f"((c)[0]), "+f"((c)[1]), "+f"((c)[2]), "+f"((c)[3]) \
                 : "r"(a0), "r"(a1), "r"(a2), "r"(a3), "r"(b0), "r"(b1))

#define STAGE_BYTES 32768
#define SMEM_TOTAL  (3 * STAGE_BYTES)
#define NCHUNK 16

// ---------------------------------------------------------------------------
// Extract U's bias column + W_d into aligned, coalesced-readable buffers
// ---------------------------------------------------------------------------
__global__ void extract_cols(const float* __restrict__ U, const float* __restrict__ W) {
    int i = threadIdx.x;               // 1024 threads
    g_Ucol[i] = U[i * 1025 + 1024];
    g_Wdc[i]  = W[1025 + i];
}

// ---------------------------------------------------------------------------
// Merged prep: blocks [0, 4096): D -> fp16 + bias partials (one warp per row)
//              blocks [4096, 5120): U^T -> fp16 (32x32 transpose tiles)
// ---------------------------------------------------------------------------
__global__ __launch_bounds__(256)
void prep_merged(const float* __restrict__ D, const float* __restrict__ U,
                 const float* __restrict__ W) {
    if (blockIdx.x < 4096) {
        // ---- D rows: convert + s1/s3 reductions ----
        int row  = (blockIdx.x * 256 + threadIdx.x) >> 5;
        int lane = threadIdx.x & 31;

        const float4* drow = (const float4*)(D + (size_t)row * DD);
        const float4* u4   = (const float4*)g_Ucol;
        const float4* wd4  = (const float4*)g_Wdc;
        uint2* dh = (uint2*)(g_Dh + (size_t)row * DD);

        float s1 = 0.f, s3 = 0.f;
        #pragma unroll
        for (int it = 0; it < 8; it++) {
            int i4 = it * 32 + lane;
            float4 d = __ldcs(&drow[i4]);          // streaming: read-once
            float4 u = u4[i4];
            float4 w = wd4[i4];
            s1 += d.x * u.x + d.y * u.y + d.z * u.z + d.w * u.w;
            s3 += d.x * w.x + d.y * w.y + d.z * w.z + d.w * w.w;

            __half2 d01 = __floats2half2_rn(d.x, d.y);
            __half2 d23 = __floats2half2_rn(d.z, d.w);
            dh[i4] = make_uint2(*(unsigned*)&d01, *(unsigned*)&d23);
        }
        #pragma unroll
        for (int o = 16; o > 0; o >>= 1) {
            s1 += __shfl_xor_sync(0xFFFFFFFFu, s1, o);
            s3 += __shfl_xor_sync(0xFFFFFFFFu, s3, o);
        }
        if (lane == 0) {
            g_bx[row] = s1 + W[1024];   // s2 (H·W_h) added by gemm_du_tc
            g_by[row] = s3;
        }
    } else {
        // ---- U^T tiles: 1024 blocks, 32x32 tile each ----
        __shared__ float t[32][33];
        int tile = blockIdx.x - 4096;           // 0..1023
        int k0 = (tile & 31) * 32, n0 = (tile >> 5) * 32;
        int tx = threadIdx.x & 31, ty = threadIdx.x >> 5;   // 32 x 8
        for (int i = ty; i < 32; i += 8)
            t[i][tx] = U[(size_t)(k0 + i) * 1025 + n0 + tx];
        __syncthreads();
        for (int i = ty; i < 32; i += 8) {
            float v = t[tx][i];
            g_Ut[(size_t)(n0 + i) * DD + k0 + tx] = __float2half_rn(v);
        }
    }
}

// ===========================================================================
// 128-thread GEMM core (4 warps, 2x2, warp tile 64x64) — used by gemm_du.
// K-chunk order rotated by `koff` (CTA parity) to de-phase barriers.
// ===========================================================================
__device__ __forceinline__ void load_chunk_128(uint32_t tile,
        const __half* Asrc, const __half* Bsrc, int tid) {
    #pragma unroll
    for (int i = 0; i < 8; i++) {
        int idx = i * 128 + tid;
        int row = idx >> 3, g = idx & 7;
        uint32_t off = (uint32_t)(row * 128 + g * 16);
        uint32_t so = off ^ ((off >> 3) & 0x70);
        cp_async16(tile + so,         (const char*)Asrc + (size_t)row * 2048 + g * 16);
        cp_async16(tile + 16384 + so, (const char*)Bsrc + (size_t)row * 2048 + g * 16);
    }
}

__device__ __forceinline__ void gemm_prologue_128(uint32_t sb,
        const __half* A, const __half* B, int tid, int koff) {
    #pragma unroll
    for (int c = 0; c < 3; c++) {
        int cc = (c + koff) & (NCHUNK - 1);
        load_chunk_128(sb + c * STAGE_BYTES, A + cc * 64, B + cc * 64, tid);
        CP_COMMIT();
    }
}

__device__ __forceinline__ void gemm_mainloop_128(uint32_t sb,
        const __half* A, const __half* B, float acc[4][8][4], int koff) {
    const int tid  = threadIdx.x;
    const int lane = tid & 31;
    const int warp = tid >> 5;
    const int wm = warp >> 1;          // 0..1
    const int wn = warp & 1;           // 0..1

    #pragma unroll
    for (int mt = 0; mt < 4; mt++)
        #pragma unroll
        for (int n8 = 0; n8 < 8; n8++)
            #pragma unroll
            for (int q = 0; q < 4; q++) acc[mt][n8][q] = 0.f;

    const int a_row = lane & 15;
    const int a_kc  = lane >> 4;
    const int b_row = (lane & 7) + ((lane >> 4) & 1) * 8;
    const int b_kc  = (lane >> 3) & 1;

    #pragma unroll 1
    for (int c = 0; c < NCHUNK; c++) {
        const int s = c % 3;
        const uint32_t tile = sb + s * STAGE_BYTES;

        if (c < NCHUNK - 2)       asm volatile("cp.async.wait_group 2;");
        else if (c == NCHUNK - 2) asm volatile("cp.async.wait_group 1;");
        else                      asm volatile("cp.async.wait_group 0;");
        __syncthreads();

        #pragma unroll
        for (int ks = 0; ks < 4; ks++) {
            uint32_t a[4][4], b[4][4];
            #pragma unroll
            for (int mt = 0; mt < 4; mt++) {
                uint32_t ad = sw_addr(tile, wm * 64 + mt * 16 + a_row, ks * 2 + a_kc);
                LDSM4(a[mt][0], a[mt][1], a[mt][2], a[mt][3], ad);
            }
            #pragma unroll
            for (int nt = 0; nt < 4; nt++) {
                uint32_t bd = sw_addr(tile + 16384, wn * 64 + nt * 16 + b_row, ks * 2 + b_kc);
                LDSM4(b[nt][0], b[nt][1], b[nt][2], b[nt][3], bd);
            }
            #pragma unroll
            for (int mt = 0; mt < 4; mt++)
                #pragma unroll
                for (int n8 = 0; n8 < 8; n8++) {
                    const int nt = n8 >> 1, h = (n8 & 1) * 2;
                    MMA16816(acc[mt][n8], a[mt][0], a[mt][1], a[mt][2], a[mt][3],
                             b[nt][h], b[nt][h + 1]);
                }
        }
        __syncthreads();

        if (c + 3 < NCHUNK) {
            int cc = (c + 3 + koff) & (NCHUNK - 1);
            load_chunk_128(tile, A + cc * 64, B + cc * 64, tid);
            CP_COMMIT();
        }
    }
}

// ===========================================================================
// 256-thread GEMM core (8 warps, 4x2, warp tile 32x64) — used by gemm_out.
// ===========================================================================
__device__ __forceinline__ void load_chunk_256(uint32_t tile,
        const __half* Asrc, const __half* Bsrc, int tid) {
    #pragma unroll
    for (int i = 0; i < 4; i++) {
        int idx = i * 256 + tid;
        int row = idx >> 3, g = idx & 7;
        uint32_t off = (uint32_t)(row * 128 + g * 16);
        uint32_t so = off ^ ((off >> 3) & 0x70);
        cp_async16(tile + so,         (const char*)Asrc + (size_t)row * 2048 + g * 16);
        cp_async16(tile + 16384 + so, (const char*)Bsrc + (size_t)row * 2048 + g * 16);
    }
}

__device__ __forceinline__ void gemm_mainloop_256(uint32_t sb,
        const __half* A, const __half* B, float acc[2][8][4], int koff) {
    const int tid  = threadIdx.x;
    const int lane = tid & 31;
    const int warp = tid >> 5;
    const int wm = warp >> 1;          // 0..3
    const int wn = warp & 1;           // 0..1

    #pragma unroll
    for (int mt = 0; mt < 2; mt++)
        #pragma unroll
        for (int n8 = 0; n8 < 8; n8++)
            #pragma unroll
            for (int q = 0; q < 4; q++) acc[mt][n8][q] = 0.f;

    #pragma unroll
    for (int c = 0; c < 3; c++) {
        int cc = (c + koff) & (NCHUNK - 1);
        load_chunk_256(sb + c * STAGE_BYTES, A + cc * 64, B + cc * 64, tid);
        CP_COMMIT();
    }

    const int a_row = lane & 15;
    const int a_kc  = lane >> 4;
    const int b_row = (lane & 7) + ((lane >> 4) & 1) * 8;
    const int b_kc  = (lane >> 3) & 1;

    #pragma unroll 1
    for (int c = 0; c < NCHUNK; c++) {
        const int s = c % 3;
        const uint32_t tile = sb + s * STAGE_BYTES;

        if (c < NCHUNK - 2)       asm volatile("cp.async.wait_group 2;");
        else if (c == NCHUNK - 2) asm volatile("cp.async.wait_group 1;");
        else                      asm volatile("cp.async.wait_group 0;");
        __syncthreads();

        #pragma unroll
        for (int ks = 0; ks < 4; ks++) {
            uint32_t a[2][4], b[4][4];
            #pragma unroll
            for (int mt = 0; mt < 2; mt++) {
                uint32_t ad = sw_addr(tile, wm * 32 + mt * 16 + a_row, ks * 2 + a_kc);
                LDSM4(a[mt][0], a[mt][1], a[mt][2], a[mt][3], ad);
            }
            #pragma unroll
            for (int nt = 0; nt < 4; nt++) {
                uint32_t bd = sw_addr(tile + 16384, wn * 64 + nt * 16 + b_row, ks * 2 + b_kc);
                LDSM4(b[nt][0], b[nt][1], b[nt][2], b[nt][3], bd);
            }
            #pragma unroll
            for (int mt = 0; mt < 2; mt++)
                #pragma unroll
                for (int n8 = 0; n8 < 8; n8++) {
                    const int nt = n8 >> 1, h = (n8 & 1) * 2;
                    MMA16816(acc[mt][n8], a[mt][0], a[mt][1], a[mt][2], a[mt][3],
                             b[nt][h], b[nt][h + 1]);
                }
        }
        __syncthreads();

        if (c + 3 < NCHUNK) {
            int cc = (c + 3 + koff) & (NCHUNK - 1);
            load_chunk_256(tile, A + cc * 64, B + cc * 64, tid);
            CP_COMMIT();
        }
    }
}

// ---------------------------------------------------------------------------
// GEMM A: DU = D @ U^T' -> fp16, with fused H->fp16 conversion + s2 bias.
// grid (8, 256), block 128.  CTA bid owns H rows [16*bid, 16*bid+16).
// ---------------------------------------------------------------------------
__global__ __launch_bounds__(128, 2)
void gemm_du_tc(const float* __restrict__ H, const float* __restrict__ W) {
    extern __shared__ char smem[];
    uint32_t sb = smem_u32(smem);

    const int tid  = threadIdx.x;
    const int lane = tid & 31;
    const int warp = tid >> 5;
    const int koff = ((blockIdx.x + blockIdx.y) & 1) * 8;

    const __half* A = g_Dh + (size_t)blockIdx.y * 128 * DD;
    const __half* B = g_Ut + (size_t)blockIdx.x * 128 * DD;

    // Issue pipeline fill first, then do H conversion under it.
    gemm_prologue_128(sb, A, B, tid, koff);

    // ---- Fused H prep: 16 rows per CTA, 4 rows per warp, warp-per-row ----
    {
        const int bid = blockIdx.y * 8 + blockIdx.x;       // 0..2047
        const float4* w4 = (const float4*)W;               // W_h = W[0..1023]
        #pragma unroll
        for (int i = 0; i < 4; i++) {
            const int row = bid * 16 + warp * 4 + i;
            const float4* hrow = (const float4*)(H + (size_t)row * DD);
            uint2* hh = (uint2*)(g_Hh + (size_t)row * DD);
            float s2 = 0.f;
            #pragma unroll
            for (int it = 0; it < 8; it++) {
                int i4 = it * 32 + lane;
                float4 h = __ldcs(&hrow[i4]);      // streaming: read-once
                float4 w = w4[i4];
                s2 += h.x * w.x + h.y * w.y + h.z * w.z + h.w * w.w;
                __half2 h01 = __floats2half2_rn(h.x, h.y);
                __half2 h23 = __floats2half2_rn(h.z, h.w);
                hh[i4] = make_uint2(*(unsigned*)&h01, *(unsigned*)&h23);
            }
            #pragma unroll
            for (int o = 16; o > 0; o >>= 1)
                s2 += __shfl_xor_sync(0xFFFFFFFFu, s2, o);
            if (lane == 0) g_bx[row] += s2;
        }
    }

    float acc[4][8][4];
    gemm_mainloop_128(sb, A, B, acc, koff);

    const int wm = warp >> 1, wn = warp & 1;
    const int gid = lane >> 2, tig = lane & 3;

    #pragma unroll
    for (int mt = 0; mt < 4; mt++) {
        #pragma unroll
        for (int h = 0; h < 2; h++) {
            const int row = blockIdx.y * 128 + wm * 64 + mt * 16 + gid + h * 8;
            #pragma unroll
            for (int n8 = 0; n8 < 8; n8++) {
                const int col = blockIdx.x * 128 + wn * 64 + n8 * 8 + tig * 2;
                __half2 v = __floats2half2_rn(acc[mt][n8][h * 2], acc[mt][n8][h * 2 + 1]);
                *(unsigned*)(g_DUh + (size_t)row * DD + col) = *(unsigned*)&v;
            }
        }
    }
}

// ---------------------------------------------------------------------------
// GEMM B: out[b] = DU[b] @ H[b]^T + bx + by.  grid (4, 4, 64), block 256.
// Batches processed in REVERSE order so the freshest (L2-resident) DUh
// blocks are consumed first.
// ---------------------------------------------------------------------------
__global__ __launch_bounds__(256, 2)
void gemm_out_tc(float* __restrict__ out) {
    extern __shared__ char smem[];
    uint32_t sb = smem_u32(smem);
    const int b = (BB - 1) - blockIdx.z;
    const int koff = ((blockIdx.x + blockIdx.y + blockIdx.z) & 1) * 8;

    const __half* A = g_DUh + ((size_t)b * NN + blockIdx.y * 128) * DD;
    const __half* B = g_Hh  + ((size_t)b * NN + blockIdx.x * 128) * DD;

    float acc[2][8][4];
    gemm_mainloop_256(sb, A, B, acc, koff);

    const int lane = threadIdx.x & 31;
    const int warp = threadIdx.x >> 5;
    const int wm = warp >> 1, wn = warp & 1;
    const int gid = lane >> 2, tig = lane & 3;

    #pragma unroll
    for (int mt = 0; mt < 2; mt++) {
        #pragma unroll
        for (int h = 0; h < 2; h++) {
            const int xg = blockIdx.y * 128 + wm * 32 + mt * 16 + gid + h * 8;
            const float bxv = g_bx[b * NN + xg];
            float* orow = out + ((size_t)b * NN + xg) * NN;
            #pragma unroll
            for (int n8 = 0; n8 < 8; n8++) {
                const int col = blockIdx.x * 128 + wn * 64 + n8 * 8 + tig * 2;
                float2 byv = *(const float2*)(g_by + b * NN + col);
                float2 v;
                v.x = acc[mt][n8][h * 2]     + bxv + byv.x;
                v.y = acc[mt][n8][h * 2 + 1] + bxv + byv.y;
                *(float2*)(orow + col) = v;
            }
        }
    }
}

// ---------------------------------------------------------------------------
// Launch (serial — stream overlap measured as a regression in R11)
// ---------------------------------------------------------------------------
extern "C" void kernel_launch(void* const* d_in, const int* in_sizes, int n_in,
                              void* d_out, int out_size) {
    const float* D = (const float*)d_in[0];
    const float* H = (const float*)d_in[1];
    const float* U = (const float*)d_in[2];
    const float* W = (const float*)d_in[3];
    float* out = (float*)d_out;

    cudaFuncSetAttribute(gemm_du_tc,  cudaFuncAttributeMaxDynamicSharedMemorySize, SMEM_TOTAL);
    cudaFuncSetAttribute(gemm_out_tc, cudaFuncAttributeMaxDynamicSharedMemorySize, SMEM_TOTAL);

    extract_cols<<<1, 1024>>>(U, W);
    prep_merged<<<4096 + 1024, 256>>>(D, U, W);

    gemm_du_tc<<<dim3(8, 256), 128, SMEM_TOTAL>>>(H, W);
    gemm_out_tc<<<dim3(4, 4, 64), 256, SMEM_TOTAL>>>(out);
}

// round 14
// speedup vs baseline: 1.8084x; 1.8084x over previous
#include <cuda_runtime.h>
#include <cuda_fp16.h>
#include <cstdint>

#define BB 64
#define NN 512
#define DD 1024
#define ROWS (BB * NN)   // 32768

// ---------------------------------------------------------------------------
// Device scratch (no runtime allocation allowed)
// ---------------------------------------------------------------------------
__device__ __half g_Dh [(size_t)ROWS * DD];
__device__ __half g_Hh [(size_t)ROWS * DD];
__device__ __half g_DUh[(size_t)ROWS * DD];
__device__ __half g_Ut [(size_t)DD * DD];    // U^T (N-major rows, K contiguous)
__device__ float g_bx[ROWS];
__device__ float g_by[ROWS];

// ---------------------------------------------------------------------------
// Helpers
// ---------------------------------------------------------------------------
__device__ __forceinline__ uint32_t smem_u32(const void* p) {
    uint32_t a;
    asm("{ .reg .u64 t; cvta.to.shared.u64 t, %1; cvt.u32.u64 %0, t; }" : "=r"(a) : "l"(p));
    return a;
}

__device__ __forceinline__ void cp_async16(uint32_t dst, const void* src) {
    asm volatile("cp.async.cg.shared.global [%0], [%1], 16;" :: "r"(dst), "l"(src));
}

#define CP_COMMIT() asm volatile("cp.async.commit_group;")

// Swizzled smem address: off = row*128 + col16*16, XOR bits[6:4] with row&7
__device__ __forceinline__ uint32_t sw_addr(uint32_t base, int row, int col16) {
    uint32_t off = (uint32_t)(row * 128 + col16 * 16);
    return base + (off ^ (((uint32_t)row & 7u) << 4));
}

#define LDSM4(r0, r1, r2, r3, addr) \
    asm volatile("ldmatrix.sync.aligned.m8n8.x4.shared.b16 {%0,%1,%2,%3}, [%4];" \
                 : "=r"(r0), "=r"(r1), "=r"(r2), "=r"(r3) : "r"(addr))

#define MMA16816(c, a0, a1, a2, a3, b0, b1) \
    asm volatile("mma.sync.aligned.m16n8k16.row.col.f32.f16.f16.f32 " \
                 "{%0,%1,%2,%3}, {%4,%5,%6,%7}, {%8,%9}, {%0,%1,%2,%3};" \
                 : "+f"((c)[0]), "+f"((c)[1]), "+f"((c)[2]), "+f"((c)[3]) \
                 : "r"(a0), "r"(a1), "r"(a2), "r"(a3), "r"(b0), "r"(b1))

#define STAGE_BYTES 32768
#define SMEM_TOTAL  (3 * STAGE_BYTES)
#define NCHUNK 16

// ---------------------------------------------------------------------------
// Prep: D -> fp16, bx partial (s1 + W[1024]), by (s3). One warp per row.
// (H conversion + s2 accumulation is fused into gemm_du_tc.)
// ---------------------------------------------------------------------------
__global__ __launch_bounds__(256)
void prep_d_bias(const float* __restrict__ D, const float* __restrict__ U,
                 const float* __restrict__ W) {
    __shared__ float sU[DD], sWd[DD];
    for (int i = threadIdx.x; i < DD; i += blockDim.x) {
        sU[i]  = U[i * 1025 + 1024];
        sWd[i] = W[1025 + i];
    }
    __syncthreads();

    int row  = (blockIdx.x * blockDim.x + threadIdx.x) >> 5;
    int lane = threadIdx.x & 31;
    if (row >= ROWS) return;

    const float4* drow = (const float4*)(D + (size_t)row * DD);
    uint2* dh = (uint2*)(g_Dh + (size_t)row * DD);

    float s1 = 0.f, s3 = 0.f;
    #pragma unroll
    for (int it = 0; it < 8; it++) {
        int i4 = it * 32 + lane;
        float4 d = drow[i4];
        int i = i4 * 4;
        s1 += d.x * sU[i]  + d.y * sU[i+1]  + d.z * sU[i+2]  + d.w * sU[i+3];
        s3 += d.x * sWd[i] + d.y * sWd[i+1] + d.z * sWd[i+2] + d.w * sWd[i+3];

        __half2 d01 = __floats2half2_rn(d.x, d.y);
        __half2 d23 = __floats2half2_rn(d.z, d.w);
        dh[i4] = make_uint2(*(unsigned*)&d01, *(unsigned*)&d23);
    }
    #pragma unroll
    for (int o = 16; o > 0; o >>= 1) {
        s1 += __shfl_xor_sync(0xFFFFFFFFu, s1, o);
        s3 += __shfl_xor_sync(0xFFFFFFFFu, s3, o);
    }
    if (lane == 0) {
        g_bx[row] = s1 + W[1024];   // s2 (H·W_h) added by gemm_du_tc
        g_by[row] = s3;
    }
}

// ---------------------------------------------------------------------------
// Prep: U^T -> fp16 (read U[k][n] stride 1025, write Ut[n][k])
// ---------------------------------------------------------------------------
__global__ void prep_u(const float* __restrict__ U) {
    __shared__ float t[32][33];
    int k0 = blockIdx.x * 32, n0 = blockIdx.y * 32;
    for (int i = threadIdx.y; i < 32; i += 8)
        t[i][threadIdx.x] = U[(size_t)(k0 + i) * 1025 + n0 + threadIdx.x];
    __syncthreads();
    for (int i = threadIdx.y; i < 32; i += 8) {
        float v = t[threadIdx.x][i];
        g_Ut[(size_t)(n0 + i) * DD + k0 + threadIdx.x] = __float2half_rn(v);
    }
}

// ===========================================================================
// 128-thread GEMM core (4 warps, 2x2, warp tile 64x64) — used by gemm_du.
// K-chunk order rotated by `koff` (CTA parity) to de-phase barriers.
// ===========================================================================
__device__ __forceinline__ void load_chunk_128(uint32_t tile,
        const __half* Asrc, const __half* Bsrc, int tid) {
    #pragma unroll
    for (int i = 0; i < 8; i++) {
        int idx = i * 128 + tid;
        int row = idx >> 3, g = idx & 7;
        uint32_t off = (uint32_t)(row * 128 + g * 16);
        uint32_t so = off ^ ((off >> 3) & 0x70);
        cp_async16(tile + so,         (const char*)Asrc + (size_t)row * 2048 + g * 16);
        cp_async16(tile + 16384 + so, (const char*)Bsrc + (size_t)row * 2048 + g * 16);
    }
}

__device__ __forceinline__ void gemm_prologue_128(uint32_t sb,
        const __half* A, const __half* B, int tid, int koff) {
    #pragma unroll
    for (int c = 0; c < 3; c++) {
        int cc = (c + koff) & (NCHUNK - 1);
        load_chunk_128(sb + c * STAGE_BYTES, A + cc * 64, B + cc * 64, tid);
        CP_COMMIT();
    }
}

__device__ __forceinline__ void gemm_mainloop_128(uint32_t sb,
        const __half* A, const __half* B, float acc[4][8][4], int koff) {
    const int tid  = threadIdx.x;
    const int lane = tid & 31;
    const int warp = tid >> 5;
    const int wm = warp >> 1;          // 0..1
    const int wn = warp & 1;           // 0..1

    #pragma unroll
    for (int mt = 0; mt < 4; mt++)
        #pragma unroll
        for (int n8 = 0; n8 < 8; n8++)
            #pragma unroll
            for (int q = 0; q < 4; q++) acc[mt][n8][q] = 0.f;

    const int a_row = lane & 15;
    const int a_kc  = lane >> 4;
    const int b_row = (lane & 7) + ((lane >> 4) & 1) * 8;
    const int b_kc  = (lane >> 3) & 1;

    #pragma unroll 1
    for (int c = 0; c < NCHUNK; c++) {
        const int s = c % 3;
        const uint32_t tile = sb + s * STAGE_BYTES;

        if (c < NCHUNK - 2)       asm volatile("cp.async.wait_group 2;");
        else if (c == NCHUNK - 2) asm volatile("cp.async.wait_group 1;");
        else                      asm volatile("cp.async.wait_group 0;");
        __syncthreads();

        #pragma unroll
        for (int ks = 0; ks < 4; ks++) {
            uint32_t a[4][4], b[4][4];
            #pragma unroll
            for (int mt = 0; mt < 4; mt++) {
                uint32_t ad = sw_addr(tile, wm * 64 + mt * 16 + a_row, ks * 2 + a_kc);
                LDSM4(a[mt][0], a[mt][1], a[mt][2], a[mt][3], ad);
            }
            #pragma unroll
            for (int nt = 0; nt < 4; nt++) {
                uint32_t bd = sw_addr(tile + 16384, wn * 64 + nt * 16 + b_row, ks * 2 + b_kc);
                LDSM4(b[nt][0], b[nt][1], b[nt][2], b[nt][3], bd);
            }
            #pragma unroll
            for (int mt = 0; mt < 4; mt++)
                #pragma unroll
                for (int n8 = 0; n8 < 8; n8++) {
                    const int nt = n8 >> 1, h = (n8 & 1) * 2;
                    MMA16816(acc[mt][n8], a[mt][0], a[mt][1], a[mt][2], a[mt][3],
                             b[nt][h], b[nt][h + 1]);
                }
        }
        __syncthreads();

        if (c + 3 < NCHUNK) {
            int cc = (c + 3 + koff) & (NCHUNK - 1);
            load_chunk_128(tile, A + cc * 64, B + cc * 64, tid);
            CP_COMMIT();
        }
    }
}

// ===========================================================================
// 256-thread GEMM core (8 warps, 4x2, warp tile 32x64) — used by gemm_out.
// ===========================================================================
__device__ __forceinline__ void load_chunk_256(uint32_t tile,
        const __half* Asrc, const __half* Bsrc, int tid) {
    #pragma unroll
    for (int i = 0; i < 4; i++) {
        int idx = i * 256 + tid;
        int row = idx >> 3, g = idx & 7;
        uint32_t off = (uint32_t)(row * 128 + g * 16);
        uint32_t so = off ^ ((off >> 3) & 0x70);
        cp_async16(tile + so,         (const char*)Asrc + (size_t)row * 2048 + g * 16);
        cp_async16(tile + 16384 + so, (const char*)Bsrc + (size_t)row * 2048 + g * 16);
    }
}

__device__ __forceinline__ void gemm_mainloop_256(uint32_t sb,
        const __half* A, const __half* B, float acc[2][8][4], int koff) {
    const int tid  = threadIdx.x;
    const int lane = tid & 31;
    const int warp = tid >> 5;
    const int wm = warp >> 1;          // 0..3
    const int wn = warp & 1;           // 0..1

    #pragma unroll
    for (int mt = 0; mt < 2; mt++)
        #pragma unroll
        for (int n8 = 0; n8 < 8; n8++)
            #pragma unroll
            for (int q = 0; q < 4; q++) acc[mt][n8][q] = 0.f;

    #pragma unroll
    for (int c = 0; c < 3; c++) {
        int cc = (c + koff) & (NCHUNK - 1);
        load_chunk_256(sb + c * STAGE_BYTES, A + cc * 64, B + cc * 64, tid);
        CP_COMMIT();
    }

    const int a_row = lane & 15;
    const int a_kc  = lane >> 4;
    const int b_row = (lane & 7) + ((lane >> 4) & 1) * 8;
    const int b_kc  = (lane >> 3) & 1;

    #pragma unroll 1
    for (int c = 0; c < NCHUNK; c++) {
        const int s = c % 3;
        const uint32_t tile = sb + s * STAGE_BYTES;

        if (c < NCHUNK - 2)       asm volatile("cp.async.wait_group 2;");
        else if (c == NCHUNK - 2) asm volatile("cp.async.wait_group 1;");
        else                      asm volatile("cp.async.wait_group 0;");
        __syncthreads();

        #pragma unroll
        for (int ks = 0; ks < 4; ks++) {
            uint32_t a[2][4], b[4][4];
            #pragma unroll
            for (int mt = 0; mt < 2; mt++) {
                uint32_t ad = sw_addr(tile, wm * 32 + mt * 16 + a_row, ks * 2 + a_kc);
                LDSM4(a[mt][0], a[mt][1], a[mt][2], a[mt][3], ad);
            }
            #pragma unroll
            for (int nt = 0; nt < 4; nt++) {
                uint32_t bd = sw_addr(tile + 16384, wn * 64 + nt * 16 + b_row, ks * 2 + b_kc);
                LDSM4(b[nt][0], b[nt][1], b[nt][2], b[nt][3], bd);
            }
            #pragma unroll
            for (int mt = 0; mt < 2; mt++)
                #pragma unroll
                for (int n8 = 0; n8 < 8; n8++) {
                    const int nt = n8 >> 1, h = (n8 & 1) * 2;
                    MMA16816(acc[mt][n8], a[mt][0], a[mt][1], a[mt][2], a[mt][3],
                             b[nt][h], b[nt][h + 1]);
                }
        }
        __syncthreads();

        if (c + 3 < NCHUNK) {
            int cc = (c + 3 + koff) & (NCHUNK - 1);
            load_chunk_256(tile, A + cc * 64, B + cc * 64, tid);
            CP_COMMIT();
        }
    }
}

// ---------------------------------------------------------------------------
// GEMM A: DU = D @ U^T' -> fp16, with fused H->fp16 conversion + s2 bias.
// grid (8, 256), block 128.  CTA bid owns H rows [16*bid, 16*bid+16).
// ---------------------------------------------------------------------------
__global__ __launch_bounds__(128, 2)
void gemm_du_tc(const float* __restrict__ H, const float* __restrict__ W) {
    extern __shared__ char smem[];
    uint32_t sb = smem_u32(smem);

    const int tid  = threadIdx.x;
    const int lane = tid & 31;
    const int warp = tid >> 5;
    const int koff = ((blockIdx.x + blockIdx.y) & 1) * 8;

    const __half* A = g_Dh + (size_t)blockIdx.y * 128 * DD;
    const __half* B = g_Ut + (size_t)blockIdx.x * 128 * DD;

    // Issue pipeline fill first, then do H conversion under it.
    gemm_prologue_128(sb, A, B, tid, koff);

    // ---- Fused H prep: 16 rows per CTA, 4 rows per warp, warp-per-row ----
    {
        const int bid = blockIdx.y * 8 + blockIdx.x;       // 0..2047
        const float4* w4 = (const float4*)W;               // W_h = W[0..1023]
        #pragma unroll
        for (int i = 0; i < 4; i++) {
            const int row = bid * 16 + warp * 4 + i;
            const float4* hrow = (const float4*)(H + (size_t)row * DD);
            uint2* hh = (uint2*)(g_Hh + (size_t)row * DD);
            float s2 = 0.f;
            #pragma unroll
            for (int it = 0; it < 8; it++) {
                int i4 = it * 32 + lane;
                float4 h = hrow[i4];
                float4 w = w4[i4];
                s2 += h.x * w.x + h.y * w.y + h.z * w.z + h.w * w.w;
                __half2 h01 = __floats2half2_rn(h.x, h.y);
                __half2 h23 = __floats2half2_rn(h.z, h.w);
                hh[i4] = make_uint2(*(unsigned*)&h01, *(unsigned*)&h23);
            }
            #pragma unroll
            for (int o = 16; o > 0; o >>= 1)
                s2 += __shfl_xor_sync(0xFFFFFFFFu, s2, o);
            if (lane == 0) g_bx[row] += s2;
        }
    }

    float acc[4][8][4];
    gemm_mainloop_128(sb, A, B, acc, koff);

    const int wm = warp >> 1, wn = warp & 1;
    const int gid = lane >> 2, tig = lane & 3;

    #pragma unroll
    for (int mt = 0; mt < 4; mt++) {
        #pragma unroll
        for (int h = 0; h < 2; h++) {
            const int row = blockIdx.y * 128 + wm * 64 + mt * 16 + gid + h * 8;
            #pragma unroll
            for (int n8 = 0; n8 < 8; n8++) {
                const int col = blockIdx.x * 128 + wn * 64 + n8 * 8 + tig * 2;
                __half2 v = __floats2half2_rn(acc[mt][n8][h * 2], acc[mt][n8][h * 2 + 1]);
                *(unsigned*)(g_DUh + (size_t)row * DD + col) = *(unsigned*)&v;
            }
        }
    }
}

// ---------------------------------------------------------------------------
// GEMM B: out[b] = DU[b] @ H[b]^T + bx + by.  grid (4, 4, 64), block 256
// ---------------------------------------------------------------------------
__global__ __launch_bounds__(256, 2)
void gemm_out_tc(float* __restrict__ out) {
    extern __shared__ char smem[];
    uint32_t sb = smem_u32(smem);
    const int b = blockIdx.z;
    const int koff = ((blockIdx.x + blockIdx.y + blockIdx.z) & 1) * 8;

    const __half* A = g_DUh + ((size_t)b * NN + blockIdx.y * 128) * DD;
    const __half* B = g_Hh  + ((size_t)b * NN + blockIdx.x * 128) * DD;

    float acc[2][8][4];
    gemm_mainloop_256(sb, A, B, acc, koff);

    const int lane = threadIdx.x & 31;
    const int warp = threadIdx.x >> 5;
    const int wm = warp >> 1, wn = warp & 1;
    const int gid = lane >> 2, tig = lane & 3;

    #pragma unroll
    for (int mt = 0; mt < 2; mt++) {
        #pragma unroll
        for (int h = 0; h < 2; h++) {
            const int xg = blockIdx.y * 128 + wm * 32 + mt * 16 + gid + h * 8;
            const float bxv = g_bx[b * NN + xg];
            float* orow = out + ((size_t)b * NN + xg) * NN;
            #pragma unroll
            for (int n8 = 0; n8 < 8; n8++) {
                const int col = blockIdx.x * 128 + wn * 64 + n8 * 8 + tig * 2;
                float2 byv = *(const float2*)(g_by + b * NN + col);
                float2 v;
                v.x = acc[mt][n8][h * 2]     + bxv + byv.x;
                v.y = acc[mt][n8][h * 2 + 1] + bxv + byv.y;
                *(float2*)(orow + col) = v;
            }
        }
    }
}

// ---------------------------------------------------------------------------
// Launch
// ---------------------------------------------------------------------------
extern "C" void kernel_launch(void* const* d_in, const int* in_sizes, int n_in,
                              void* d_out, int out_size) {
    const float* D = (const float*)d_in[0];
    const float* H = (const float*)d_in[1];
    const float* U = (const float*)d_in[2];
    const float* W = (const float*)d_in[3];
    float* out = (float*)d_out;

    cudaFuncSetAttribute(gemm_du_tc,  cudaFuncAttributeMaxDynamicSharedMemorySize, SMEM_TOTAL);
    cudaFuncSetAttribute(gemm_out_tc, cudaFuncAttributeMaxDynamicSharedMemorySize, SMEM_TOTAL);

    prep_d_bias<<<(ROWS * 32) / 256, 256>>>(D, U, W);
    prep_u<<<dim3(32, 32), dim3(32, 8)>>>(U);

    gemm_du_tc<<<dim3(8, 256), 128, SMEM_TOTAL>>>(H, W);
    gemm_out_tc<<<dim3(4, 4, 64), 256, SMEM_TOTAL>>>(out);
}